// round 1
// baseline (speedup 1.0000x reference)
#include <cuda_runtime.h>
#include <cuda_bf16.h>
#include <cstdint>

#define N_USER 100000
#define N_BIZ  50000
#define NEDGE  500000
#define D_IN   256
#define D_H    512
#define D_OUT  256

// ---------------- scratch (static device globals; no runtime allocation) ----
__device__ float g_sum_biz1[(size_t)N_BIZ * D_IN];    // 51.2 MB
__device__ float g_sum_user1[(size_t)N_USER * D_IN];  // 102.4 MB
__device__ float g_h_biz[(size_t)N_BIZ * D_H];        // 102.4 MB
__device__ float g_h_user[(size_t)N_USER * D_H];      // 204.8 MB
__device__ float g_sum_biz2[(size_t)N_BIZ * D_H];     // 102.4 MB
__device__ float g_sum_user2[(size_t)N_USER * D_H];   // 204.8 MB
__device__ float g_deg_biz[N_BIZ];
__device__ float g_deg_user[N_USER];

// ---------------- degree ----------------------------------------------------
__global__ void degree_kernel(const int* __restrict__ e_src,
                              const int* __restrict__ e_dst,
                              float* __restrict__ deg_user,
                              float* __restrict__ deg_biz, int E) {
    int i = blockIdx.x * blockDim.x + threadIdx.x;
    if (i < E) {
        atomicAdd(&deg_user[e_src[i]], 1.0f);
        atomicAdd(&deg_biz[e_dst[i]], 1.0f);
    }
}

// in-place: deg -> 1/max(deg,1)
__global__ void invdeg_kernel(float* __restrict__ deg, int n) {
    int i = blockIdx.x * blockDim.x + threadIdx.x;
    if (i < n) deg[i] = 1.0f / fmaxf(deg[i], 1.0f);
}

// ---------------- scatter-add aggregation ----------------------------------
// one thread = one float4 chunk of one edge's message
__global__ void scatter_add_kernel(const float* __restrict__ feat,
                                   const int* __restrict__ gidx,
                                   const int* __restrict__ sidx,
                                   float* __restrict__ out,
                                   int E, int log2d4) {
    int idx = blockIdx.x * blockDim.x + threadIdx.x;
    int total = E << log2d4;
    if (idx >= total) return;
    int e = idx >> log2d4;
    int c = idx & ((1 << log2d4) - 1);
    int g = gidx[e];
    int s = sidx[e];
    float4 v = ((const float4*)feat)[((size_t)g << log2d4) + c];
    float* o = out + ((((size_t)s << log2d4) + c) << 2);
    atomicAdd(o + 0, v.x);
    atomicAdd(o + 1, v.y);
    atomicAdd(o + 2, v.z);
    atomicAdd(o + 3, v.w);
}

// ---------------- fused SAGE GEMM -------------------------------------------
// out = relu( (A * invdeg[row]) @ Wl + X @ Wr + bias )
// A,X: [M,K] row-major. Wl,Wr: [K,N] row-major. out: [M,N].
// 128x128 block tile, BK=8, 8x8 microtile (split-64 mapping), 256 threads.
__global__ void __launch_bounds__(256, 2)
sage_gemm_kernel(const float* __restrict__ A, const float* __restrict__ invdeg,
                 const float* __restrict__ X,
                 const float* __restrict__ Wl, const float* __restrict__ Wr,
                 const float* __restrict__ bias, float* __restrict__ out,
                 int M, int K, int N) {
    __shared__ float As[8][132];  // +4 pad: conflict-free transposed stores
    __shared__ float Bs[8][128];

    const int tid = threadIdx.x;
    const int bm = blockIdx.y * 128;
    const int bn = blockIdx.x * 128;
    const int tx = tid & 15;   // n dim
    const int ty = tid >> 4;   // m dim
    const int la_row = tid >> 1;          // 0..127
    const int la_col = (tid & 1) << 2;    // 0 or 4
    const int lb_row = tid >> 5;          // 0..7
    const int lb_col = (tid & 31) << 2;   // 0..124

    float acc[8][8];
#pragma unroll
    for (int i = 0; i < 8; i++)
#pragma unroll
        for (int j = 0; j < 8; j++) acc[i][j] = 0.0f;

    const int arow = bm + la_row;
    const bool arow_ok = (arow < M);

#pragma unroll 1
    for (int pass = 0; pass < 2; ++pass) {
        const float* Am = pass ? X : A;
        const float* W = pass ? Wr : Wl;
        float scale = 1.0f;
        if (pass == 0 && arow_ok) scale = invdeg[arow];
        const float* arow_ptr = arow_ok ? (Am + (size_t)arow * K) : nullptr;

        for (int k0 = 0; k0 < K; k0 += 8) {
            float4 av = make_float4(0.f, 0.f, 0.f, 0.f);
            if (arow_ok) av = *(const float4*)(arow_ptr + k0 + la_col);
            As[la_col + 0][la_row] = av.x * scale;
            As[la_col + 1][la_row] = av.y * scale;
            As[la_col + 2][la_row] = av.z * scale;
            As[la_col + 3][la_row] = av.w * scale;

            float4 bv = *(const float4*)(W + (size_t)(k0 + lb_row) * N + bn + lb_col);
            *(float4*)(&Bs[lb_row][lb_col]) = bv;
            __syncthreads();

#pragma unroll
            for (int k = 0; k < 8; ++k) {
                float a[8], b[8];
                *(float4*)(a)     = *(const float4*)(&As[k][ty * 4]);
                *(float4*)(a + 4) = *(const float4*)(&As[k][64 + ty * 4]);
                *(float4*)(b)     = *(const float4*)(&Bs[k][tx * 4]);
                *(float4*)(b + 4) = *(const float4*)(&Bs[k][64 + tx * 4]);
#pragma unroll
                for (int i = 0; i < 8; i++)
#pragma unroll
                    for (int j = 0; j < 8; j++) acc[i][j] += a[i] * b[j];
            }
            __syncthreads();
        }
    }

    // epilogue: bias + relu, vectorized stores
    float bvs[8];
#pragma unroll
    for (int j = 0; j < 4; j++) {
        bvs[j]     = bias[bn + tx * 4 + j];
        bvs[4 + j] = bias[bn + 64 + tx * 4 + j];
    }
#pragma unroll
    for (int i = 0; i < 8; i++) {
        int r = (i < 4) ? (bm + ty * 4 + i) : (bm + 64 + ty * 4 + (i - 4));
        if (r < M) {
            float4 o0, o1;
            o0.x = fmaxf(acc[i][0] + bvs[0], 0.f);
            o0.y = fmaxf(acc[i][1] + bvs[1], 0.f);
            o0.z = fmaxf(acc[i][2] + bvs[2], 0.f);
            o0.w = fmaxf(acc[i][3] + bvs[3], 0.f);
            o1.x = fmaxf(acc[i][4] + bvs[4], 0.f);
            o1.y = fmaxf(acc[i][5] + bvs[5], 0.f);
            o1.z = fmaxf(acc[i][6] + bvs[6], 0.f);
            o1.w = fmaxf(acc[i][7] + bvs[7], 0.f);
            *(float4*)(out + (size_t)r * N + bn + tx * 4) = o0;
            *(float4*)(out + (size_t)r * N + bn + 64 + tx * 4) = o1;
        }
    }
}

// ---------------- launch -----------------------------------------------------
extern "C" void kernel_launch(void* const* d_in, const int* in_sizes, int n_in,
                              void* d_out, int out_size) {
    const float* x_user = (const float*)d_in[0];
    const float* x_biz  = (const float*)d_in[1];
    const int* e_src = (const int*)d_in[2];
    const int* e_dst = (const int*)d_in[3];
    const float* W1_l_ub = (const float*)d_in[4];
    const float* W1_r_ub = (const float*)d_in[5];
    const float* b1_ub   = (const float*)d_in[6];
    const float* W1_l_bu = (const float*)d_in[7];
    const float* W1_r_bu = (const float*)d_in[8];
    const float* b1_bu   = (const float*)d_in[9];
    const float* W2_l_ub = (const float*)d_in[10];
    const float* W2_r_ub = (const float*)d_in[11];
    const float* b2_ub   = (const float*)d_in[12];
    const float* W2_l_bu = (const float*)d_in[13];
    const float* W2_r_bu = (const float*)d_in[14];
    const float* b2_bu   = (const float*)d_in[15];

    float* o_user = (float*)d_out;
    float* o_biz  = (float*)d_out + (size_t)N_USER * D_OUT;

    float *sum_b1, *sum_u1, *h_biz, *h_user, *sum_b2, *sum_u2, *deg_b, *deg_u;
    cudaGetSymbolAddress((void**)&sum_b1, g_sum_biz1);
    cudaGetSymbolAddress((void**)&sum_u1, g_sum_user1);
    cudaGetSymbolAddress((void**)&h_biz,  g_h_biz);
    cudaGetSymbolAddress((void**)&h_user, g_h_user);
    cudaGetSymbolAddress((void**)&sum_b2, g_sum_biz2);
    cudaGetSymbolAddress((void**)&sum_u2, g_sum_user2);
    cudaGetSymbolAddress((void**)&deg_b,  g_deg_biz);
    cudaGetSymbolAddress((void**)&deg_u,  g_deg_user);

    // zero accumulators + degree counters
    cudaMemsetAsync(sum_b1, 0, (size_t)N_BIZ * D_IN * 4);
    cudaMemsetAsync(sum_u1, 0, (size_t)N_USER * D_IN * 4);
    cudaMemsetAsync(sum_b2, 0, (size_t)N_BIZ * D_H * 4);
    cudaMemsetAsync(sum_u2, 0, (size_t)N_USER * D_H * 4);
    cudaMemsetAsync(deg_b, 0, (size_t)N_BIZ * 4);
    cudaMemsetAsync(deg_u, 0, (size_t)N_USER * 4);

    // degrees -> inverse degrees
    degree_kernel<<<(NEDGE + 255) / 256, 256>>>(e_src, e_dst, deg_u, deg_b, NEDGE);
    invdeg_kernel<<<(N_USER + 255) / 256, 256>>>(deg_u, N_USER);
    invdeg_kernel<<<(N_BIZ + 255) / 256, 256>>>(deg_b, N_BIZ);

    // layer-1 aggregation (D_IN=256 -> 64 float4 chunks, log2=6)
    {
        int total = NEDGE << 6;
        scatter_add_kernel<<<(total + 255) / 256, 256>>>(x_user, e_src, e_dst, sum_b1, NEDGE, 6);
        scatter_add_kernel<<<(total + 255) / 256, 256>>>(x_biz, e_dst, e_src, sum_u1, NEDGE, 6);
    }

    // layer-1 GEMMs: [*,256] @ [256,512]
    {
        dim3 grid_b(D_H / 128, (N_BIZ + 127) / 128);
        sage_gemm_kernel<<<grid_b, 256>>>(sum_b1, deg_b, x_biz, W1_l_ub, W1_r_ub,
                                          b1_ub, h_biz, N_BIZ, D_IN, D_H);
        dim3 grid_u(D_H / 128, (N_USER + 127) / 128);
        sage_gemm_kernel<<<grid_u, 256>>>(sum_u1, deg_u, x_user, W1_l_bu, W1_r_bu,
                                          b1_bu, h_user, N_USER, D_IN, D_H);
    }

    // layer-2 aggregation (D_H=512 -> 128 float4 chunks, log2=7)
    {
        int total = NEDGE << 7;
        scatter_add_kernel<<<(total + 255) / 256, 256>>>(h_user, e_src, e_dst, sum_b2, NEDGE, 7);
        scatter_add_kernel<<<(total + 255) / 256, 256>>>(h_biz, e_dst, e_src, sum_u2, NEDGE, 7);
    }

    // layer-2 GEMMs: [*,512] @ [512,256]
    {
        dim3 grid_b(D_OUT / 128, (N_BIZ + 127) / 128);
        sage_gemm_kernel<<<grid_b, 256>>>(sum_b2, deg_b, h_biz, W2_l_ub, W2_r_ub,
                                          b2_ub, o_biz, N_BIZ, D_H, D_OUT);
        dim3 grid_u(D_OUT / 128, (N_USER + 127) / 128);
        sage_gemm_kernel<<<grid_u, 256>>>(sum_u2, deg_u, h_user, W2_l_bu, W2_r_bu,
                                          b2_bu, o_user, N_USER, D_H, D_OUT);
    }
}

// round 3
// speedup vs baseline: 1.6544x; 1.6544x over previous
#include <cuda_runtime.h>
#include <cstdint>

#define N_USER 100000
#define N_BIZ  50000
#define NEDGE  500000
#define D_IN   256
#define D_H    512
#define D_OUT  256

// ---------------- scratch (static device globals; no runtime allocation) ----
__device__ float g_sum_biz1[(size_t)N_BIZ * D_IN];
__device__ float g_sum_user1[(size_t)N_USER * D_IN];
__device__ float g_h_biz[(size_t)N_BIZ * D_H];
__device__ float g_h_user[(size_t)N_USER * D_H];
__device__ float g_sum_biz2[(size_t)N_BIZ * D_H];
__device__ float g_sum_user2[(size_t)N_USER * D_H];
__device__ float g_deg_biz[N_BIZ];
__device__ float g_deg_user[N_USER];
__device__ float g_wt[8 * 131072];   // 8 transposed (and tf32-rounded) weights

// ---------------- helpers ----------------------------------------------------
static __device__ __forceinline__ float tf32_rn(float x) {
    uint32_t r;
    asm("cvt.rna.tf32.f32 %0, %1;" : "=r"(r) : "f"(x));
    return __uint_as_float(r);
}
static __device__ __forceinline__ void mma_tf32(float* d, const float* a, const float* b) {
    asm volatile(
        "mma.sync.aligned.m16n8k8.row.col.f32.tf32.tf32.f32 "
        "{%0,%1,%2,%3}, {%4,%5,%6,%7}, {%8,%9}, {%0,%1,%2,%3};"
        : "+f"(d[0]), "+f"(d[1]), "+f"(d[2]), "+f"(d[3])
        : "r"(__float_as_uint(a[0])), "r"(__float_as_uint(a[1])),
          "r"(__float_as_uint(a[2])), "r"(__float_as_uint(a[3])),
          "r"(__float_as_uint(b[0])), "r"(__float_as_uint(b[1])));
}

// ---------------- degree ----------------------------------------------------
__global__ void degree_kernel(const int* __restrict__ e_src,
                              const int* __restrict__ e_dst,
                              float* __restrict__ deg_user,
                              float* __restrict__ deg_biz, int E) {
    int i = blockIdx.x * blockDim.x + threadIdx.x;
    if (i < E) {
        atomicAdd(&deg_user[e_src[i]], 1.0f);
        atomicAdd(&deg_biz[e_dst[i]], 1.0f);
    }
}
__global__ void invdeg_kernel(float* __restrict__ deg, int n) {
    int i = blockIdx.x * blockDim.x + threadIdx.x;
    if (i < n) deg[i] = 1.0f / fmaxf(deg[i], 1.0f);
}

// ------- weight transpose + tf32 round: W[K,N] -> Wt[N,K] (tf32 bits) -------
__global__ void transpose_kernel(const float* __restrict__ W,
                                 float* __restrict__ Wt, int K, int N) {
    __shared__ float t[32][33];
    int n0 = blockIdx.x * 32, k0 = blockIdx.y * 32;
    int tx = threadIdx.x, ty = threadIdx.y;
#pragma unroll
    for (int i = 0; i < 4; i++)
        t[ty + i * 8][tx] = W[(size_t)(k0 + ty + i * 8) * N + n0 + tx];
    __syncthreads();
#pragma unroll
    for (int i = 0; i < 4; i++)
        Wt[(size_t)(n0 + ty + i * 8) * K + k0 + tx] = tf32_rn(t[tx][ty + i * 8]);
}

// ---------------- scatter-add with vector red --------------------------------
__global__ void scatter_add_kernel(const float* __restrict__ feat,
                                   const int* __restrict__ gidx,
                                   const int* __restrict__ sidx,
                                   float* __restrict__ out,
                                   int E, int log2d4) {
    int idx = blockIdx.x * blockDim.x + threadIdx.x;
    int total = E << log2d4;
    if (idx >= total) return;
    int e = idx >> log2d4;
    int c = idx & ((1 << log2d4) - 1);
    int g = __ldg(gidx + e);
    int s = __ldg(sidx + e);
    float4 v = __ldg((const float4*)feat + ((size_t)g << log2d4) + c);
    float4* o = (float4*)out + ((size_t)s << log2d4) + c;
    asm volatile("red.global.add.v4.f32 [%0], {%1, %2, %3, %4};"
                 :: "l"(o), "f"(v.x), "f"(v.y), "f"(v.z), "f"(v.w) : "memory");
}

// ---------------- tf32 mma.sync fused SAGE GEMM ------------------------------
// out = relu( (A*invdeg) @ Wl + X @ Wr + bias )
// A,X: [M,K] row-major fp32. Wtl,Wtr: [N,K] row-major, tf32-rounded.
// CTA 128x128, BK=32 double-buffered. Warp grid 2(M)x4(N): 64x32 per warp.
// A split hi/lo tf32 (2-term), B single tf32.
#define SM_STRIDE 36
#define SM_MAT    (128 * SM_STRIDE)          // floats per matrix
#define SM_BUF    (3 * SM_MAT)               // Ahi, Alo, B
#define SMEM_BYTES (2 * SM_BUF * 4)          // 110592 B

__global__ void __launch_bounds__(256)
sage_mma_kernel(const float* __restrict__ A, const float* __restrict__ invdeg,
                const float* __restrict__ X, const float* __restrict__ Wtl,
                const float* __restrict__ Wtr, const float* __restrict__ bias,
                float* __restrict__ out, int M, int K, int N) {
    extern __shared__ float sm[];
    const int tid = threadIdx.x;
    const int lane = tid & 31, wid = tid >> 5;
    const int wm = wid >> 2, wn = wid & 3;
    const int g = lane >> 2, t = lane & 3;

    const int bm = blockIdx.y * 128, bn = blockIdx.x * 128;
    const int srow = tid >> 1;
    const int sbase = (tid & 1) * 16;
    const int grow = bm + srow;
    const bool rok = grow < M;
    const float inv = rok ? invdeg[grow] : 0.0f;

    const float* arow[2];
    arow[0] = A + (size_t)(rok ? grow : 0) * K;
    arow[1] = X + (size_t)(rok ? grow : 0) * K;
    const float* brow[2];
    brow[0] = Wtl + (size_t)(bn + srow) * K;
    brow[1] = Wtr + (size_t)(bn + srow) * K;

    const int CH = K >> 5;       // 32-wide chunks per pass
    const int T = 2 * CH;

    float acc[4][4][4];
#pragma unroll
    for (int i = 0; i < 4; i++)
#pragma unroll
        for (int j = 0; j < 4; j++)
#pragma unroll
            for (int r = 0; r < 4; r++) acc[i][j][r] = 0.0f;

    // ---- staging ----
    auto stage = [&](int cc, int buf) {
        const int pass = (cc >= CH) ? 1 : 0;
        const int k0 = (cc - pass * CH) << 5;
        const float scl = pass ? 1.0f : inv;
        float* Ahi = sm + buf * SM_BUF;
        float* Alo = Ahi + SM_MAT;
        float* Bs = Ahi + 2 * SM_MAT;
        const float* ap = arow[pass] + k0 + sbase;
        const float* bp = brow[pass] + k0 + sbase;
        const int so = srow * SM_STRIDE + sbase;
#pragma unroll
        for (int j = 0; j < 4; j++) {
            float4 v = make_float4(0.f, 0.f, 0.f, 0.f);
            if (rok) v = __ldg((const float4*)(ap + j * 4));
            v.x *= scl; v.y *= scl; v.z *= scl; v.w *= scl;
            float4 h, l;
            h.x = tf32_rn(v.x); l.x = tf32_rn(v.x - h.x);
            h.y = tf32_rn(v.y); l.y = tf32_rn(v.y - h.y);
            h.z = tf32_rn(v.z); l.z = tf32_rn(v.z - h.z);
            h.w = tf32_rn(v.w); l.w = tf32_rn(v.w - h.w);
            *(float4*)(Ahi + so + j * 4) = h;
            *(float4*)(Alo + so + j * 4) = l;
            *(float4*)(Bs + so + j * 4) = __ldg((const float4*)(bp + j * 4));
        }
    };

    // ---- compute one staged chunk ----
    auto compute = [&](int buf) {
        float* Ahi = sm + buf * SM_BUF;
        float* Alo = Ahi + SM_MAT;
        float* Bs = Ahi + 2 * SM_MAT;
#pragma unroll
        for (int ks = 0; ks < 4; ++ks) {
            const int kb = ks * 8;
            float bfr[4][2];
#pragma unroll
            for (int nt = 0; nt < 4; ++nt) {
                const int n0 = wn * 32 + nt * 8 + g;
                bfr[nt][0] = Bs[n0 * SM_STRIDE + kb + t];
                bfr[nt][1] = Bs[n0 * SM_STRIDE + kb + t + 4];
            }
#pragma unroll
            for (int s = 0; s < 2; ++s) {
                float* As = s ? Alo : Ahi;
                float afr[4][4];
#pragma unroll
                for (int mt = 0; mt < 4; ++mt) {
                    const int m0 = wm * 64 + mt * 16 + g;
                    afr[mt][0] = As[m0 * SM_STRIDE + kb + t];
                    afr[mt][1] = As[(m0 + 8) * SM_STRIDE + kb + t];
                    afr[mt][2] = As[m0 * SM_STRIDE + kb + t + 4];
                    afr[mt][3] = As[(m0 + 8) * SM_STRIDE + kb + t + 4];
                }
#pragma unroll
                for (int mt = 0; mt < 4; ++mt)
#pragma unroll
                    for (int nt = 0; nt < 4; ++nt)
                        mma_tf32(acc[mt][nt], afr[mt], bfr[nt]);
            }
        }
    };

    stage(0, 0);
    __syncthreads();
#pragma unroll 1
    for (int cc = 0; cc < T; ++cc) {
        if (cc + 1 < T) stage(cc + 1, (cc + 1) & 1);
        compute(cc & 1);
        __syncthreads();
    }

    // ---- epilogue: bias + relu ----
#pragma unroll
    for (int mt = 0; mt < 4; ++mt) {
#pragma unroll
        for (int rr = 0; rr < 2; ++rr) {
            const int r = bm + wm * 64 + mt * 16 + g + rr * 8;
            if (r < M) {
                float* orow = out + (size_t)r * N + bn + wn * 32;
                const float* brw = bias + bn + wn * 32;
#pragma unroll
                for (int nt = 0; nt < 4; ++nt) {
                    const int c = nt * 8 + t * 2;
                    float2 o;
                    o.x = fmaxf(acc[mt][nt][rr * 2 + 0] + brw[c], 0.f);
                    o.y = fmaxf(acc[mt][nt][rr * 2 + 1] + brw[c + 1], 0.f);
                    *(float2*)(orow + c) = o;
                }
            }
        }
    }
}

// ---------------- launch -----------------------------------------------------
extern "C" void kernel_launch(void* const* d_in, const int* in_sizes, int n_in,
                              void* d_out, int out_size) {
    const float* x_user = (const float*)d_in[0];
    const float* x_biz  = (const float*)d_in[1];
    const int* e_src = (const int*)d_in[2];
    const int* e_dst = (const int*)d_in[3];
    const float* W1_l_ub = (const float*)d_in[4];
    const float* W1_r_ub = (const float*)d_in[5];
    const float* b1_ub   = (const float*)d_in[6];
    const float* W1_l_bu = (const float*)d_in[7];
    const float* W1_r_bu = (const float*)d_in[8];
    const float* b1_bu   = (const float*)d_in[9];
    const float* W2_l_ub = (const float*)d_in[10];
    const float* W2_r_ub = (const float*)d_in[11];
    const float* b2_ub   = (const float*)d_in[12];
    const float* W2_l_bu = (const float*)d_in[13];
    const float* W2_r_bu = (const float*)d_in[14];
    const float* b2_bu   = (const float*)d_in[15];

    float* o_user = (float*)d_out;
    float* o_biz  = (float*)d_out + (size_t)N_USER * D_OUT;

    float *sum_b1, *sum_u1, *h_biz, *h_user, *sum_b2, *sum_u2, *deg_b, *deg_u, *wt;
    cudaGetSymbolAddress((void**)&sum_b1, g_sum_biz1);
    cudaGetSymbolAddress((void**)&sum_u1, g_sum_user1);
    cudaGetSymbolAddress((void**)&h_biz,  g_h_biz);
    cudaGetSymbolAddress((void**)&h_user, g_h_user);
    cudaGetSymbolAddress((void**)&sum_b2, g_sum_biz2);
    cudaGetSymbolAddress((void**)&sum_u2, g_sum_user2);
    cudaGetSymbolAddress((void**)&deg_b,  g_deg_biz);
    cudaGetSymbolAddress((void**)&deg_u,  g_deg_user);
    cudaGetSymbolAddress((void**)&wt,     g_wt);

    cudaFuncSetAttribute(sage_mma_kernel,
                         cudaFuncAttributeMaxDynamicSharedMemorySize, SMEM_BYTES);

    // transpose + tf32-round the 8 weight matrices into [N,K] scratch
    {
        dim3 blk(32, 8);
        dim3 g1(D_H / 32, D_IN / 32);
        dim3 g2(D_OUT / 32, D_H / 32);
        transpose_kernel<<<g1, blk>>>(W1_l_ub, wt + 0 * 131072, D_IN, D_H);
        transpose_kernel<<<g1, blk>>>(W1_r_ub, wt + 1 * 131072, D_IN, D_H);
        transpose_kernel<<<g1, blk>>>(W1_l_bu, wt + 2 * 131072, D_IN, D_H);
        transpose_kernel<<<g1, blk>>>(W1_r_bu, wt + 3 * 131072, D_IN, D_H);
        transpose_kernel<<<g2, blk>>>(W2_l_ub, wt + 4 * 131072, D_H, D_OUT);
        transpose_kernel<<<g2, blk>>>(W2_r_ub, wt + 5 * 131072, D_H, D_OUT);
        transpose_kernel<<<g2, blk>>>(W2_l_bu, wt + 6 * 131072, D_H, D_OUT);
        transpose_kernel<<<g2, blk>>>(W2_r_bu, wt + 7 * 131072, D_H, D_OUT);
    }

    cudaMemsetAsync(sum_b1, 0, (size_t)N_BIZ * D_IN * 4);
    cudaMemsetAsync(sum_u1, 0, (size_t)N_USER * D_IN * 4);
    cudaMemsetAsync(sum_b2, 0, (size_t)N_BIZ * D_H * 4);
    cudaMemsetAsync(sum_u2, 0, (size_t)N_USER * D_H * 4);
    cudaMemsetAsync(deg_b, 0, (size_t)N_BIZ * 4);
    cudaMemsetAsync(deg_u, 0, (size_t)N_USER * 4);

    degree_kernel<<<(NEDGE + 255) / 256, 256>>>(e_src, e_dst, deg_u, deg_b, NEDGE);
    invdeg_kernel<<<(N_USER + 255) / 256, 256>>>(deg_u, N_USER);
    invdeg_kernel<<<(N_BIZ + 255) / 256, 256>>>(deg_b, N_BIZ);

    // layer-1 aggregation
    {
        int total = NEDGE << 6;
        scatter_add_kernel<<<(total + 255) / 256, 256>>>(x_user, e_src, e_dst, sum_b1, NEDGE, 6);
        scatter_add_kernel<<<(total + 255) / 256, 256>>>(x_biz, e_dst, e_src, sum_u1, NEDGE, 6);
    }

    // layer-1 GEMMs: [*,256] -> [*,512]
    {
        dim3 gb(D_H / 128, (N_BIZ + 127) / 128);
        sage_mma_kernel<<<gb, 256, SMEM_BYTES>>>(sum_b1, deg_b, x_biz,
            wt + 0 * 131072, wt + 1 * 131072, b1_ub, h_biz, N_BIZ, D_IN, D_H);
        dim3 gu(D_H / 128, (N_USER + 127) / 128);
        sage_mma_kernel<<<gu, 256, SMEM_BYTES>>>(sum_u1, deg_u, x_user,
            wt + 2 * 131072, wt + 3 * 131072, b1_bu, h_user, N_USER, D_IN, D_H);
    }

    // layer-2 aggregation
    {
        int total = NEDGE << 7;
        scatter_add_kernel<<<(total + 255) / 256, 256>>>(h_user, e_src, e_dst, sum_b2, NEDGE, 7);
        scatter_add_kernel<<<(total + 255) / 256, 256>>>(h_biz, e_dst, e_src, sum_u2, NEDGE, 7);
    }

    // layer-2 GEMMs: [*,512] -> [*,256]
    {
        dim3 gb(D_OUT / 128, (N_BIZ + 127) / 128);
        sage_mma_kernel<<<gb, 256, SMEM_BYTES>>>(sum_b2, deg_b, h_biz,
            wt + 4 * 131072, wt + 5 * 131072, b2_ub, o_biz, N_BIZ, D_H, D_OUT);
        dim3 gu(D_OUT / 128, (N_USER + 127) / 128);
        sage_mma_kernel<<<gu, 256, SMEM_BYTES>>>(sum_u2, deg_u, h_user,
            wt + 6 * 131072, wt + 7 * 131072, b2_bu, o_user, N_USER, D_H, D_OUT);
    }
}

// round 4
// speedup vs baseline: 2.4714x; 1.4938x over previous
#include <cuda_runtime.h>
#include <cstdint>

#define N_USER 100000
#define N_BIZ  50000
#define NEDGE  500000
#define D_IN   256
#define D_H    512
#define D_OUT  256

// ---------------- scratch (static device globals) ----------------------------
__device__ float g_sum_biz1[(size_t)N_BIZ * D_IN];
__device__ float g_sum_user1[(size_t)N_USER * D_IN];
__device__ float g_h_biz[(size_t)N_BIZ * D_H];
__device__ float g_h_user[(size_t)N_USER * D_H];
__device__ float g_sum_biz2[(size_t)N_BIZ * D_H];
__device__ float g_sum_user2[(size_t)N_USER * D_H];
__device__ float g_inv_biz[N_BIZ];
__device__ float g_inv_user[N_USER];
__device__ float g_wt[8 * 131072];
// CSR scratch
__device__ int g_cnt_user[N_USER];
__device__ int g_cnt_biz[N_BIZ];
__device__ int g_off_user[N_USER + 1];
__device__ int g_off_biz[N_BIZ + 1];
__device__ int g_cur_user[N_USER];
__device__ int g_cur_biz[N_BIZ];
__device__ int g_adj_user[NEDGE];   // per user: list of biz neighbors
__device__ int g_adj_biz[NEDGE];    // per biz: list of user neighbors

// ---------------- helpers ----------------------------------------------------
static __device__ __forceinline__ float tf32_rn(float x) {
    uint32_t r;
    asm("cvt.rna.tf32.f32 %0, %1;" : "=r"(r) : "f"(x));
    return __uint_as_float(r);
}
static __device__ __forceinline__ void mma_tf32(float* d, const float* a, const float* b) {
    asm volatile(
        "mma.sync.aligned.m16n8k8.row.col.f32.tf32.tf32.f32 "
        "{%0,%1,%2,%3}, {%4,%5,%6,%7}, {%8,%9}, {%0,%1,%2,%3};"
        : "+f"(d[0]), "+f"(d[1]), "+f"(d[2]), "+f"(d[3])
        : "r"(__float_as_uint(a[0])), "r"(__float_as_uint(a[1])),
          "r"(__float_as_uint(a[2])), "r"(__float_as_uint(a[3])),
          "r"(__float_as_uint(b[0])), "r"(__float_as_uint(b[1])));
}

// ---------------- CSR build --------------------------------------------------
__global__ void hist_kernel(const int* __restrict__ e_src,
                            const int* __restrict__ e_dst,
                            int* __restrict__ cnt_u, int* __restrict__ cnt_b, int E) {
    int i = blockIdx.x * blockDim.x + threadIdx.x;
    if (i < E) {
        atomicAdd(&cnt_u[e_src[i]], 1);
        atomicAdd(&cnt_b[e_dst[i]], 1);
    }
}

// single-block exclusive scan (n up to ~100001), writes off[0..n] and cur[0..n-1]
__global__ void scan_kernel(const int* __restrict__ cnt, int* __restrict__ off,
                            int* __restrict__ cur, int n) {
    __shared__ int wsum[32];
    __shared__ int carry_s;
    const int tid = threadIdx.x, lane = tid & 31, wid = tid >> 5;
    if (tid == 0) carry_s = 0;
    __syncthreads();
    for (int base = 0; base < n; base += 1024) {
        const int i = base + tid;
        const int v = (i < n) ? cnt[i] : 0;
        int x = v;
#pragma unroll
        for (int s = 1; s < 32; s <<= 1) {
            int y = __shfl_up_sync(0xFFFFFFFFu, x, s);
            if (lane >= s) x += y;
        }
        if (lane == 31) wsum[wid] = x;
        __syncthreads();
        if (wid == 0) {
            int w = wsum[lane];
#pragma unroll
            for (int s = 1; s < 32; s <<= 1) {
                int y = __shfl_up_sync(0xFFFFFFFFu, w, s);
                if (lane >= s) w += y;
            }
            wsum[lane] = w;
        }
        __syncthreads();
        const int woff = (wid == 0) ? 0 : wsum[wid - 1];
        const int excl = carry_s + woff + x - v;
        if (i < n) { off[i] = excl; cur[i] = excl; }
        __syncthreads();
        if (tid == 0) carry_s += wsum[31];
        __syncthreads();
    }
    if (tid == 0) off[n] = carry_s;
}

__global__ void fill_kernel(const int* __restrict__ e_src,
                            const int* __restrict__ e_dst,
                            int* __restrict__ cur_u, int* __restrict__ cur_b,
                            int* __restrict__ adj_u, int* __restrict__ adj_b, int E) {
    int i = blockIdx.x * blockDim.x + threadIdx.x;
    if (i < E) {
        const int s = e_src[i], d = e_dst[i];
        adj_b[atomicAdd(&cur_b[d], 1)] = s;
        adj_u[atomicAdd(&cur_u[s], 1)] = d;
    }
}

__global__ void invdeg_kernel(const int* __restrict__ off, float* __restrict__ inv, int n) {
    int i = blockIdx.x * blockDim.x + threadIdx.x;
    if (i < n) inv[i] = 1.0f / fmaxf((float)(off[i + 1] - off[i]), 1.0f);
}

// ---------------- gather aggregation (no atomics) ----------------------------
// grid = n_dst, blockDim = d4 (float4 columns per row)
__global__ void gather_sum_kernel(const float4* __restrict__ feat,
                                  const int* __restrict__ off,
                                  const int* __restrict__ adj,
                                  float4* __restrict__ out, int d4) {
    const int n = blockIdx.x;
    const int tid = threadIdx.x;
    const int s = __ldg(off + n), e = __ldg(off + n + 1);
    float4 a0 = make_float4(0.f, 0.f, 0.f, 0.f);
    float4 a1 = make_float4(0.f, 0.f, 0.f, 0.f);
    int i = s;
    for (; i + 1 < e; i += 2) {
        const int s0 = __ldg(adj + i), s1 = __ldg(adj + i + 1);
        const float4 v0 = __ldg(feat + (size_t)s0 * d4 + tid);
        const float4 v1 = __ldg(feat + (size_t)s1 * d4 + tid);
        a0.x += v0.x; a0.y += v0.y; a0.z += v0.z; a0.w += v0.w;
        a1.x += v1.x; a1.y += v1.y; a1.z += v1.z; a1.w += v1.w;
    }
    if (i < e) {
        const int s0 = __ldg(adj + i);
        const float4 v0 = __ldg(feat + (size_t)s0 * d4 + tid);
        a0.x += v0.x; a0.y += v0.y; a0.z += v0.z; a0.w += v0.w;
    }
    a0.x += a1.x; a0.y += a1.y; a0.z += a1.z; a0.w += a1.w;
    out[(size_t)n * d4 + tid] = a0;
}

// ------- weight transpose + tf32 round: W[K,N] -> Wt[N,K] --------------------
__global__ void transpose_kernel(const float* __restrict__ W,
                                 float* __restrict__ Wt, int K, int N) {
    __shared__ float t[32][33];
    int n0 = blockIdx.x * 32, k0 = blockIdx.y * 32;
    int tx = threadIdx.x, ty = threadIdx.y;
#pragma unroll
    for (int i = 0; i < 4; i++)
        t[ty + i * 8][tx] = W[(size_t)(k0 + ty + i * 8) * N + n0 + tx];
    __syncthreads();
#pragma unroll
    for (int i = 0; i < 4; i++)
        Wt[(size_t)(n0 + ty + i * 8) * K + k0 + tx] = tf32_rn(t[tx][ty + i * 8]);
}

// ---------------- tf32 mma.sync fused SAGE GEMM (single tf32) ----------------
// out = relu( (A*invdeg) @ Wl + X @ Wr + bias )
// A,X: [M,K] fp32 row-major. Wtl,Wtr: [N,K] tf32-rounded. CTA 128x128, BK=32.
// Warp grid 2(M)x4(N): 64x32 per warp.
#define SM_STRIDE 36
#define SM_MAT    (128 * SM_STRIDE)
#define SM_BUF    (2 * SM_MAT)               // A, B
#define SMEM_BYTES (2 * SM_BUF * 4)          // 73728 B

__global__ void __launch_bounds__(256)
sage_mma_kernel(const float* __restrict__ A, const float* __restrict__ invdeg,
                const float* __restrict__ X, const float* __restrict__ Wtl,
                const float* __restrict__ Wtr, const float* __restrict__ bias,
                float* __restrict__ out, int M, int K, int N) {
    extern __shared__ float sm[];
    const int tid = threadIdx.x;
    const int lane = tid & 31, wid = tid >> 5;
    const int wm = wid >> 2, wn = wid & 3;
    const int g = lane >> 2, t = lane & 3;

    const int bm = blockIdx.y * 128, bn = blockIdx.x * 128;
    const int srow = tid >> 1;
    const int sbase = (tid & 1) * 16;
    const int grow = bm + srow;
    const bool rok = grow < M;
    const float inv = rok ? invdeg[grow] : 0.0f;

    const float* arow[2];
    arow[0] = A + (size_t)(rok ? grow : 0) * K;
    arow[1] = X + (size_t)(rok ? grow : 0) * K;
    const float* brow[2];
    brow[0] = Wtl + (size_t)(bn + srow) * K;
    brow[1] = Wtr + (size_t)(bn + srow) * K;

    const int CH = K >> 5;
    const int T = 2 * CH;

    float acc[4][4][4];
#pragma unroll
    for (int i = 0; i < 4; i++)
#pragma unroll
        for (int j = 0; j < 4; j++)
#pragma unroll
            for (int r = 0; r < 4; r++) acc[i][j][r] = 0.0f;

    auto stage = [&](int cc, int buf) {
        const int pass = (cc >= CH) ? 1 : 0;
        const int k0 = (cc - pass * CH) << 5;
        const float scl = pass ? 1.0f : inv;
        float* As = sm + buf * SM_BUF;
        float* Bs = As + SM_MAT;
        const float* ap = arow[pass] + k0 + sbase;
        const float* bp = brow[pass] + k0 + sbase;
        const int so = srow * SM_STRIDE + sbase;
#pragma unroll
        for (int j = 0; j < 4; j++) {
            float4 v = make_float4(0.f, 0.f, 0.f, 0.f);
            if (rok) v = __ldg((const float4*)(ap + j * 4));
            float4 h;
            h.x = tf32_rn(v.x * scl);
            h.y = tf32_rn(v.y * scl);
            h.z = tf32_rn(v.z * scl);
            h.w = tf32_rn(v.w * scl);
            *(float4*)(As + so + j * 4) = h;
            *(float4*)(Bs + so + j * 4) = __ldg((const float4*)(bp + j * 4));
        }
    };

    auto compute = [&](int buf) {
        float* As = sm + buf * SM_BUF;
        float* Bs = As + SM_MAT;
#pragma unroll
        for (int ks = 0; ks < 4; ++ks) {
            const int kb = ks * 8;
            float bfr[4][2];
#pragma unroll
            for (int nt = 0; nt < 4; ++nt) {
                const int n0 = wn * 32 + nt * 8 + g;
                bfr[nt][0] = Bs[n0 * SM_STRIDE + kb + t];
                bfr[nt][1] = Bs[n0 * SM_STRIDE + kb + t + 4];
            }
            float afr[4][4];
#pragma unroll
            for (int mt = 0; mt < 4; ++mt) {
                const int m0 = wm * 64 + mt * 16 + g;
                afr[mt][0] = As[m0 * SM_STRIDE + kb + t];
                afr[mt][1] = As[(m0 + 8) * SM_STRIDE + kb + t];
                afr[mt][2] = As[m0 * SM_STRIDE + kb + t + 4];
                afr[mt][3] = As[(m0 + 8) * SM_STRIDE + kb + t + 4];
            }
#pragma unroll
            for (int mt = 0; mt < 4; ++mt)
#pragma unroll
                for (int nt = 0; nt < 4; ++nt)
                    mma_tf32(acc[mt][nt], afr[mt], bfr[nt]);
        }
    };

    stage(0, 0);
    __syncthreads();
#pragma unroll 1
    for (int cc = 0; cc < T; ++cc) {
        if (cc + 1 < T) stage(cc + 1, (cc + 1) & 1);
        compute(cc & 1);
        __syncthreads();
    }

#pragma unroll
    for (int mt = 0; mt < 4; ++mt) {
#pragma unroll
        for (int rr = 0; rr < 2; ++rr) {
            const int r = bm + wm * 64 + mt * 16 + g + rr * 8;
            if (r < M) {
                float* orow = out + (size_t)r * N + bn + wn * 32;
                const float* brw = bias + bn + wn * 32;
#pragma unroll
                for (int nt = 0; nt < 4; ++nt) {
                    const int c = nt * 8 + t * 2;
                    float2 o;
                    o.x = fmaxf(acc[mt][nt][rr * 2 + 0] + brw[c], 0.f);
                    o.y = fmaxf(acc[mt][nt][rr * 2 + 1] + brw[c + 1], 0.f);
                    *(float2*)(orow + c) = o;
                }
            }
        }
    }
}

// ---------------- launch -----------------------------------------------------
extern "C" void kernel_launch(void* const* d_in, const int* in_sizes, int n_in,
                              void* d_out, int out_size) {
    const float* x_user = (const float*)d_in[0];
    const float* x_biz  = (const float*)d_in[1];
    const int* e_src = (const int*)d_in[2];
    const int* e_dst = (const int*)d_in[3];
    const float* W1_l_ub = (const float*)d_in[4];
    const float* W1_r_ub = (const float*)d_in[5];
    const float* b1_ub   = (const float*)d_in[6];
    const float* W1_l_bu = (const float*)d_in[7];
    const float* W1_r_bu = (const float*)d_in[8];
    const float* b1_bu   = (const float*)d_in[9];
    const float* W2_l_ub = (const float*)d_in[10];
    const float* W2_r_ub = (const float*)d_in[11];
    const float* b2_ub   = (const float*)d_in[12];
    const float* W2_l_bu = (const float*)d_in[13];
    const float* W2_r_bu = (const float*)d_in[14];
    const float* b2_bu   = (const float*)d_in[15];

    float* o_user = (float*)d_out;
    float* o_biz  = (float*)d_out + (size_t)N_USER * D_OUT;

    float *sum_b1, *sum_u1, *h_biz, *h_user, *sum_b2, *sum_u2, *inv_b, *inv_u, *wt;
    int *cnt_u, *cnt_b, *off_u, *off_b, *cur_u, *cur_b, *adj_u, *adj_b;
    cudaGetSymbolAddress((void**)&sum_b1, g_sum_biz1);
    cudaGetSymbolAddress((void**)&sum_u1, g_sum_user1);
    cudaGetSymbolAddress((void**)&h_biz,  g_h_biz);
    cudaGetSymbolAddress((void**)&h_user, g_h_user);
    cudaGetSymbolAddress((void**)&sum_b2, g_sum_biz2);
    cudaGetSymbolAddress((void**)&sum_u2, g_sum_user2);
    cudaGetSymbolAddress((void**)&inv_b,  g_inv_biz);
    cudaGetSymbolAddress((void**)&inv_u,  g_inv_user);
    cudaGetSymbolAddress((void**)&wt,     g_wt);
    cudaGetSymbolAddress((void**)&cnt_u,  g_cnt_user);
    cudaGetSymbolAddress((void**)&cnt_b,  g_cnt_biz);
    cudaGetSymbolAddress((void**)&off_u,  g_off_user);
    cudaGetSymbolAddress((void**)&off_b,  g_off_biz);
    cudaGetSymbolAddress((void**)&cur_u,  g_cur_user);
    cudaGetSymbolAddress((void**)&cur_b,  g_cur_biz);
    cudaGetSymbolAddress((void**)&adj_u,  g_adj_user);
    cudaGetSymbolAddress((void**)&adj_b,  g_adj_biz);

    cudaFuncSetAttribute(sage_mma_kernel,
                         cudaFuncAttributeMaxDynamicSharedMemorySize, SMEM_BYTES);

    // weight transpose + tf32 round
    {
        dim3 blk(32, 8);
        dim3 g1(D_H / 32, D_IN / 32);
        dim3 g2(D_OUT / 32, D_H / 32);
        transpose_kernel<<<g1, blk>>>(W1_l_ub, wt + 0 * 131072, D_IN, D_H);
        transpose_kernel<<<g1, blk>>>(W1_r_ub, wt + 1 * 131072, D_IN, D_H);
        transpose_kernel<<<g1, blk>>>(W1_l_bu, wt + 2 * 131072, D_IN, D_H);
        transpose_kernel<<<g1, blk>>>(W1_r_bu, wt + 3 * 131072, D_IN, D_H);
        transpose_kernel<<<g2, blk>>>(W2_l_ub, wt + 4 * 131072, D_H, D_OUT);
        transpose_kernel<<<g2, blk>>>(W2_r_ub, wt + 5 * 131072, D_H, D_OUT);
        transpose_kernel<<<g2, blk>>>(W2_l_bu, wt + 6 * 131072, D_H, D_OUT);
        transpose_kernel<<<g2, blk>>>(W2_r_bu, wt + 7 * 131072, D_H, D_OUT);
    }

    // CSR build
    cudaMemsetAsync(cnt_u, 0, N_USER * sizeof(int));
    cudaMemsetAsync(cnt_b, 0, N_BIZ * sizeof(int));
    hist_kernel<<<(NEDGE + 255) / 256, 256>>>(e_src, e_dst, cnt_u, cnt_b, NEDGE);
    scan_kernel<<<1, 1024>>>(cnt_u, off_u, cur_u, N_USER);
    scan_kernel<<<1, 1024>>>(cnt_b, off_b, cur_b, N_BIZ);
    fill_kernel<<<(NEDGE + 255) / 256, 256>>>(e_src, e_dst, cur_u, cur_b,
                                              adj_u, adj_b, NEDGE);
    invdeg_kernel<<<(N_USER + 255) / 256, 256>>>(off_u, inv_u, N_USER);
    invdeg_kernel<<<(N_BIZ + 255) / 256, 256>>>(off_b, inv_b, N_BIZ);

    // layer-1 aggregation (gather)
    gather_sum_kernel<<<N_BIZ, D_IN / 4>>>((const float4*)x_user, off_b, adj_b,
                                           (float4*)sum_b1, D_IN / 4);
    gather_sum_kernel<<<N_USER, D_IN / 4>>>((const float4*)x_biz, off_u, adj_u,
                                            (float4*)sum_u1, D_IN / 4);

    // layer-1 GEMMs: [*,256] -> [*,512]
    {
        dim3 gb(D_H / 128, (N_BIZ + 127) / 128);
        sage_mma_kernel<<<gb, 256, SMEM_BYTES>>>(sum_b1, inv_b, x_biz,
            wt + 0 * 131072, wt + 1 * 131072, b1_ub, h_biz, N_BIZ, D_IN, D_H);
        dim3 gu(D_H / 128, (N_USER + 127) / 128);
        sage_mma_kernel<<<gu, 256, SMEM_BYTES>>>(sum_u1, inv_u, x_user,
            wt + 2 * 131072, wt + 3 * 131072, b1_bu, h_user, N_USER, D_IN, D_H);
    }

    // layer-2 aggregation (gather)
    gather_sum_kernel<<<N_BIZ, D_H / 4>>>((const float4*)h_user, off_b, adj_b,
                                          (float4*)sum_b2, D_H / 4);
    gather_sum_kernel<<<N_USER, D_H / 4>>>((const float4*)h_biz, off_u, adj_u,
                                           (float4*)sum_u2, D_H / 4);

    // layer-2 GEMMs: [*,512] -> [*,256]
    {
        dim3 gb(D_OUT / 128, (N_BIZ + 127) / 128);
        sage_mma_kernel<<<gb, 256, SMEM_BYTES>>>(sum_b2, inv_b, h_biz,
            wt + 4 * 131072, wt + 5 * 131072, b2_ub, o_biz, N_BIZ, D_H, D_OUT);
        dim3 gu(D_OUT / 128, (N_USER + 127) / 128);
        sage_mma_kernel<<<gu, 256, SMEM_BYTES>>>(sum_u2, inv_u, h_user,
            wt + 6 * 131072, wt + 7 * 131072, b2_bu, o_user, N_USER, D_H, D_OUT);
    }
}

// round 5
// speedup vs baseline: 2.6655x; 1.0785x over previous
#include <cuda_runtime.h>
#include <cstdint>

#define N_USER 100000
#define N_BIZ  50000
#define NEDGE  500000
#define D_IN   256
#define D_H    512
#define D_OUT  256

// ---------------- scratch (static device globals) ----------------------------
__device__ float g_sum_biz1[(size_t)N_BIZ * D_IN];
__device__ float g_sum_user1[(size_t)N_USER * D_IN];
__device__ float g_h_biz[(size_t)N_BIZ * D_H];
__device__ float g_h_user[(size_t)N_USER * D_H];
__device__ float g_sum_biz2[(size_t)N_BIZ * D_H];
__device__ float g_sum_user2[(size_t)N_USER * D_H];
__device__ float g_xt_user[(size_t)N_USER * D_IN];
__device__ float g_xt_biz[(size_t)N_BIZ * D_IN];
__device__ float g_inv_biz[N_BIZ];
__device__ float g_inv_user[N_USER];
__device__ float g_wt[8 * 131072];
// CSR scratch
__device__ int g_cnt_user[N_USER];
__device__ int g_cnt_biz[N_BIZ];
__device__ int g_off_user[N_USER + 1];
__device__ int g_off_biz[N_BIZ + 1];
__device__ int g_cur_user[N_USER];
__device__ int g_cur_biz[N_BIZ];
__device__ int g_adj_user[NEDGE];
__device__ int g_adj_biz[NEDGE];

// ---------------- helpers ----------------------------------------------------
static __device__ __forceinline__ float tf32_rn(float x) {
    uint32_t r;
    asm("cvt.rna.tf32.f32 %0, %1;" : "=r"(r) : "f"(x));
    return __uint_as_float(r);
}
static __device__ __forceinline__ void mma_tf32(float* d, const float* a, const float* b) {
    asm volatile(
        "mma.sync.aligned.m16n8k8.row.col.f32.tf32.tf32.f32 "
        "{%0,%1,%2,%3}, {%4,%5,%6,%7}, {%8,%9}, {%0,%1,%2,%3};"
        : "+f"(d[0]), "+f"(d[1]), "+f"(d[2]), "+f"(d[3])
        : "r"(__float_as_uint(a[0])), "r"(__float_as_uint(a[1])),
          "r"(__float_as_uint(a[2])), "r"(__float_as_uint(a[3])),
          "r"(__float_as_uint(b[0])), "r"(__float_as_uint(b[1])));
}
static __device__ __forceinline__ void cp16(void* sdst, const void* gsrc, bool pred) {
    uint32_t s;
    asm("{ .reg .u64 t; cvta.to.shared.u64 t, %1; cvt.u32.u64 %0, t; }"
        : "=r"(s) : "l"(sdst));
    const int sz = pred ? 16 : 0;
    asm volatile("cp.async.cg.shared.global [%0], [%1], 16, %2;"
                 :: "r"(s), "l"(gsrc), "r"(sz) : "memory");
}

// ---------------- CSR build --------------------------------------------------
__global__ void hist_kernel(const int* __restrict__ e_src,
                            const int* __restrict__ e_dst,
                            int* __restrict__ cnt_u, int* __restrict__ cnt_b, int E) {
    int i = blockIdx.x * blockDim.x + threadIdx.x;
    if (i < E) {
        atomicAdd(&cnt_u[e_src[i]], 1);
        atomicAdd(&cnt_b[e_dst[i]], 1);
    }
}

__global__ void scan_kernel(const int* __restrict__ cnt, int* __restrict__ off,
                            int* __restrict__ cur, int n) {
    __shared__ int wsum[32];
    __shared__ int carry_s;
    const int tid = threadIdx.x, lane = tid & 31, wid = tid >> 5;
    if (tid == 0) carry_s = 0;
    __syncthreads();
    for (int base = 0; base < n; base += 1024) {
        const int i = base + tid;
        const int v = (i < n) ? cnt[i] : 0;
        int x = v;
#pragma unroll
        for (int s = 1; s < 32; s <<= 1) {
            int y = __shfl_up_sync(0xFFFFFFFFu, x, s);
            if (lane >= s) x += y;
        }
        if (lane == 31) wsum[wid] = x;
        __syncthreads();
        if (wid == 0) {
            int w = wsum[lane];
#pragma unroll
            for (int s = 1; s < 32; s <<= 1) {
                int y = __shfl_up_sync(0xFFFFFFFFu, w, s);
                if (lane >= s) w += y;
            }
            wsum[lane] = w;
        }
        __syncthreads();
        const int woff = (wid == 0) ? 0 : wsum[wid - 1];
        const int excl = carry_s + woff + x - v;
        if (i < n) { off[i] = excl; cur[i] = excl; }
        __syncthreads();
        if (tid == 0) carry_s += wsum[31];
        __syncthreads();
    }
    if (tid == 0) off[n] = carry_s;
}

__global__ void fill_kernel(const int* __restrict__ e_src,
                            const int* __restrict__ e_dst,
                            int* __restrict__ cur_u, int* __restrict__ cur_b,
                            int* __restrict__ adj_u, int* __restrict__ adj_b, int E) {
    int i = blockIdx.x * blockDim.x + threadIdx.x;
    if (i < E) {
        const int s = e_src[i], d = e_dst[i];
        adj_b[atomicAdd(&cur_b[d], 1)] = s;
        adj_u[atomicAdd(&cur_u[s], 1)] = d;
    }
}

__global__ void invdeg_kernel(const int* __restrict__ off, float* __restrict__ inv, int n) {
    int i = blockIdx.x * blockDim.x + threadIdx.x;
    if (i < n) inv[i] = 1.0f / fmaxf((float)(off[i + 1] - off[i]), 1.0f);
}

// ---------------- elementwise tf32 round -------------------------------------
__global__ void round_tf32_kernel(const float4* __restrict__ in,
                                  float4* __restrict__ out, int n4) {
    int i = blockIdx.x * blockDim.x + threadIdx.x;
    if (i < n4) {
        float4 v = __ldg(in + i);
        v.x = tf32_rn(v.x); v.y = tf32_rn(v.y);
        v.z = tf32_rn(v.z); v.w = tf32_rn(v.w);
        out[i] = v;
    }
}

// ---------------- gather-mean aggregation (writes tf32-rounded mean) ---------
__global__ void gather_mean_kernel(const float4* __restrict__ feat,
                                   const int* __restrict__ off,
                                   const int* __restrict__ adj,
                                   const float* __restrict__ inv,
                                   float4* __restrict__ out, int d4) {
    const int n = blockIdx.x;
    const int tid = threadIdx.x;
    const int s = __ldg(off + n), e = __ldg(off + n + 1);
    float4 a0 = make_float4(0.f, 0.f, 0.f, 0.f);
    float4 a1 = make_float4(0.f, 0.f, 0.f, 0.f);
    int i = s;
    for (; i + 1 < e; i += 2) {
        const int s0 = __ldg(adj + i), s1 = __ldg(adj + i + 1);
        const float4 v0 = __ldg(feat + (size_t)s0 * d4 + tid);
        const float4 v1 = __ldg(feat + (size_t)s1 * d4 + tid);
        a0.x += v0.x; a0.y += v0.y; a0.z += v0.z; a0.w += v0.w;
        a1.x += v1.x; a1.y += v1.y; a1.z += v1.z; a1.w += v1.w;
    }
    if (i < e) {
        const int s0 = __ldg(adj + i);
        const float4 v0 = __ldg(feat + (size_t)s0 * d4 + tid);
        a0.x += v0.x; a0.y += v0.y; a0.z += v0.z; a0.w += v0.w;
    }
    const float sc = __ldg(inv + n);
    float4 o;
    o.x = tf32_rn((a0.x + a1.x) * sc);
    o.y = tf32_rn((a0.y + a1.y) * sc);
    o.z = tf32_rn((a0.z + a1.z) * sc);
    o.w = tf32_rn((a0.w + a1.w) * sc);
    out[(size_t)n * d4 + tid] = o;
}

// ------- weight transpose + tf32 round: W[K,N] -> Wt[N,K] --------------------
__global__ void transpose_kernel(const float* __restrict__ W,
                                 float* __restrict__ Wt, int K, int N) {
    __shared__ float t[32][33];
    int n0 = blockIdx.x * 32, k0 = blockIdx.y * 32;
    int tx = threadIdx.x, ty = threadIdx.y;
#pragma unroll
    for (int i = 0; i < 4; i++)
        t[ty + i * 8][tx] = W[(size_t)(k0 + ty + i * 8) * N + n0 + tx];
    __syncthreads();
#pragma unroll
    for (int i = 0; i < 4; i++)
        Wt[(size_t)(n0 + ty + i * 8) * K + k0 + tx] = tf32_rn(t[tx][ty + i * 8]);
}

// ---------------- tf32 mma.sync fused SAGE GEMM (cp.async pipelined) ---------
// out = relu( A @ Wl + X @ Wr + bias );  A = tf32 mean (pre-scaled/rounded),
// X = tf32-rounded features. Wtl,Wtr: [N,K] tf32. CTA 128x128, BK=32, 3-stage.
#define SM_STRIDE 36
#define SM_MAT    (128 * SM_STRIDE)
#define SM_BUF    (2 * SM_MAT)                // A, B per stage
#define N_STAGE   3
#define SMEM_BYTES (N_STAGE * SM_BUF * 4)     // 110592 B

__global__ void __launch_bounds__(256, 2)
sage_mma_kernel(const float* __restrict__ A, const float* __restrict__ X,
                const float* __restrict__ Wtl, const float* __restrict__ Wtr,
                const float* __restrict__ bias, float* __restrict__ out,
                int M, int K, int N, int round_out) {
    extern __shared__ float sm[];
    const int tid = threadIdx.x;
    const int lane = tid & 31, wid = tid >> 5;
    const int wm = wid >> 2, wn = wid & 3;
    const int g = lane >> 2, t = lane & 3;

    const int bm = blockIdx.y * 128, bn = blockIdx.x * 128;
    const int srow = tid >> 1;
    const int sbase = (tid & 1) * 16;
    const int grow = bm + srow;
    const bool rok = grow < M;

    const float* arow[2];
    arow[0] = A + (size_t)(rok ? grow : 0) * K;
    arow[1] = X + (size_t)(rok ? grow : 0) * K;
    const float* brow[2];
    brow[0] = Wtl + (size_t)(bn + srow) * K;
    brow[1] = Wtr + (size_t)(bn + srow) * K;

    const int CH = K >> 5;
    const int T = 2 * CH;

    float acc[4][4][4];
#pragma unroll
    for (int i = 0; i < 4; i++)
#pragma unroll
        for (int j = 0; j < 4; j++)
#pragma unroll
            for (int r = 0; r < 4; r++) acc[i][j][r] = 0.0f;

    auto stage = [&](int cc, int buf) {
        const int pass = (cc >= CH) ? 1 : 0;
        const int k0 = (cc - pass * CH) << 5;
        float* As = sm + buf * SM_BUF;
        float* Bs = As + SM_MAT;
        const float* ap = arow[pass] + k0 + sbase;
        const float* bp = brow[pass] + k0 + sbase;
        const int so = srow * SM_STRIDE + sbase;
#pragma unroll
        for (int j = 0; j < 4; j++) {
            cp16(As + so + j * 4, ap + j * 4, rok);
            cp16(Bs + so + j * 4, bp + j * 4, true);
        }
    };

    auto compute = [&](int buf) {
        float* As = sm + buf * SM_BUF;
        float* Bs = As + SM_MAT;
#pragma unroll
        for (int ks = 0; ks < 4; ++ks) {
            const int kb = ks * 8;
            float bfr[4][2];
#pragma unroll
            for (int nt = 0; nt < 4; ++nt) {
                const int n0 = wn * 32 + nt * 8 + g;
                bfr[nt][0] = Bs[n0 * SM_STRIDE + kb + t];
                bfr[nt][1] = Bs[n0 * SM_STRIDE + kb + t + 4];
            }
            float afr[4][4];
#pragma unroll
            for (int mt = 0; mt < 4; ++mt) {
                const int m0 = wm * 64 + mt * 16 + g;
                afr[mt][0] = As[m0 * SM_STRIDE + kb + t];
                afr[mt][1] = As[(m0 + 8) * SM_STRIDE + kb + t];
                afr[mt][2] = As[m0 * SM_STRIDE + kb + t + 4];
                afr[mt][3] = As[(m0 + 8) * SM_STRIDE + kb + t + 4];
            }
#pragma unroll
            for (int mt = 0; mt < 4; ++mt)
#pragma unroll
                for (int nt = 0; nt < 4; ++nt)
                    mma_tf32(acc[mt][nt], afr[mt], bfr[nt]);
        }
    };

    // prologue: stages 0, 1
    stage(0, 0);
    asm volatile("cp.async.commit_group;" ::: "memory");
    stage(1, 1);
    asm volatile("cp.async.commit_group;" ::: "memory");

#pragma unroll 1
    for (int cc = 0; cc < T; ++cc) {
        asm volatile("cp.async.wait_group %0;" :: "n"(1) : "memory");
        __syncthreads();
        if (cc + 2 < T) stage(cc + 2, (cc + 2) % N_STAGE);
        asm volatile("cp.async.commit_group;" ::: "memory");
        compute(cc % N_STAGE);
    }

    // epilogue
#pragma unroll
    for (int mt = 0; mt < 4; ++mt) {
#pragma unroll
        for (int rr = 0; rr < 2; ++rr) {
            const int r = bm + wm * 64 + mt * 16 + g + rr * 8;
            if (r < M) {
                float* orow = out + (size_t)r * N + bn + wn * 32;
                const float* brw = bias + bn + wn * 32;
#pragma unroll
                for (int nt = 0; nt < 4; ++nt) {
                    const int c = nt * 8 + t * 2;
                    float2 o;
                    o.x = fmaxf(acc[mt][nt][rr * 2 + 0] + brw[c], 0.f);
                    o.y = fmaxf(acc[mt][nt][rr * 2 + 1] + brw[c + 1], 0.f);
                    if (round_out) { o.x = tf32_rn(o.x); o.y = tf32_rn(o.y); }
                    *(float2*)(orow + c) = o;
                }
            }
        }
    }
}

// ---------------- launch -----------------------------------------------------
extern "C" void kernel_launch(void* const* d_in, const int* in_sizes, int n_in,
                              void* d_out, int out_size) {
    const float* x_user = (const float*)d_in[0];
    const float* x_biz  = (const float*)d_in[1];
    const int* e_src = (const int*)d_in[2];
    const int* e_dst = (const int*)d_in[3];
    const float* W1_l_ub = (const float*)d_in[4];
    const float* W1_r_ub = (const float*)d_in[5];
    const float* b1_ub   = (const float*)d_in[6];
    const float* W1_l_bu = (const float*)d_in[7];
    const float* W1_r_bu = (const float*)d_in[8];
    const float* b1_bu   = (const float*)d_in[9];
    const float* W2_l_ub = (const float*)d_in[10];
    const float* W2_r_ub = (const float*)d_in[11];
    const float* b2_ub   = (const float*)d_in[12];
    const float* W2_l_bu = (const float*)d_in[13];
    const float* W2_r_bu = (const float*)d_in[14];
    const float* b2_bu   = (const float*)d_in[15];

    float* o_user = (float*)d_out;
    float* o_biz  = (float*)d_out + (size_t)N_USER * D_OUT;

    float *sum_b1, *sum_u1, *h_biz, *h_user, *sum_b2, *sum_u2;
    float *xt_u, *xt_b, *inv_b, *inv_u, *wt;
    int *cnt_u, *cnt_b, *off_u, *off_b, *cur_u, *cur_b, *adj_u, *adj_b;
    cudaGetSymbolAddress((void**)&sum_b1, g_sum_biz1);
    cudaGetSymbolAddress((void**)&sum_u1, g_sum_user1);
    cudaGetSymbolAddress((void**)&h_biz,  g_h_biz);
    cudaGetSymbolAddress((void**)&h_user, g_h_user);
    cudaGetSymbolAddress((void**)&sum_b2, g_sum_biz2);
    cudaGetSymbolAddress((void**)&sum_u2, g_sum_user2);
    cudaGetSymbolAddress((void**)&xt_u,   g_xt_user);
    cudaGetSymbolAddress((void**)&xt_b,   g_xt_biz);
    cudaGetSymbolAddress((void**)&inv_b,  g_inv_biz);
    cudaGetSymbolAddress((void**)&inv_u,  g_inv_user);
    cudaGetSymbolAddress((void**)&wt,     g_wt);
    cudaGetSymbolAddress((void**)&cnt_u,  g_cnt_user);
    cudaGetSymbolAddress((void**)&cnt_b,  g_cnt_biz);
    cudaGetSymbolAddress((void**)&off_u,  g_off_user);
    cudaGetSymbolAddress((void**)&off_b,  g_off_biz);
    cudaGetSymbolAddress((void**)&cur_u,  g_cur_user);
    cudaGetSymbolAddress((void**)&cur_b,  g_cur_biz);
    cudaGetSymbolAddress((void**)&adj_u,  g_adj_user);
    cudaGetSymbolAddress((void**)&adj_b,  g_adj_biz);

    cudaFuncSetAttribute(sage_mma_kernel,
                         cudaFuncAttributeMaxDynamicSharedMemorySize, SMEM_BYTES);

    // weight transpose + tf32 round
    {
        dim3 blk(32, 8);
        dim3 g1(D_H / 32, D_IN / 32);
        dim3 g2(D_OUT / 32, D_H / 32);
        transpose_kernel<<<g1, blk>>>(W1_l_ub, wt + 0 * 131072, D_IN, D_H);
        transpose_kernel<<<g1, blk>>>(W1_r_ub, wt + 1 * 131072, D_IN, D_H);
        transpose_kernel<<<g1, blk>>>(W1_l_bu, wt + 2 * 131072, D_IN, D_H);
        transpose_kernel<<<g1, blk>>>(W1_r_bu, wt + 3 * 131072, D_IN, D_H);
        transpose_kernel<<<g2, blk>>>(W2_l_ub, wt + 4 * 131072, D_H, D_OUT);
        transpose_kernel<<<g2, blk>>>(W2_r_ub, wt + 5 * 131072, D_H, D_OUT);
        transpose_kernel<<<g2, blk>>>(W2_l_bu, wt + 6 * 131072, D_H, D_OUT);
        transpose_kernel<<<g2, blk>>>(W2_r_bu, wt + 7 * 131072, D_H, D_OUT);
    }

    // pre-round x features to tf32 copies
    {
        int n4u = N_USER * D_IN / 4, n4b = N_BIZ * D_IN / 4;
        round_tf32_kernel<<<(n4u + 255) / 256, 256>>>((const float4*)x_user,
                                                      (float4*)xt_u, n4u);
        round_tf32_kernel<<<(n4b + 255) / 256, 256>>>((const float4*)x_biz,
                                                      (float4*)xt_b, n4b);
    }

    // CSR build
    cudaMemsetAsync(cnt_u, 0, N_USER * sizeof(int));
    cudaMemsetAsync(cnt_b, 0, N_BIZ * sizeof(int));
    hist_kernel<<<(NEDGE + 255) / 256, 256>>>(e_src, e_dst, cnt_u, cnt_b, NEDGE);
    scan_kernel<<<1, 1024>>>(cnt_u, off_u, cur_u, N_USER);
    scan_kernel<<<1, 1024>>>(cnt_b, off_b, cur_b, N_BIZ);
    fill_kernel<<<(NEDGE + 255) / 256, 256>>>(e_src, e_dst, cur_u, cur_b,
                                              adj_u, adj_b, NEDGE);
    invdeg_kernel<<<(N_USER + 255) / 256, 256>>>(off_u, inv_u, N_USER);
    invdeg_kernel<<<(N_BIZ + 255) / 256, 256>>>(off_b, inv_b, N_BIZ);

    // layer-1 aggregation (mean, tf32-rounded)
    gather_mean_kernel<<<N_BIZ, D_IN / 4>>>((const float4*)x_user, off_b, adj_b,
                                            inv_b, (float4*)sum_b1, D_IN / 4);
    gather_mean_kernel<<<N_USER, D_IN / 4>>>((const float4*)x_biz, off_u, adj_u,
                                             inv_u, (float4*)sum_u1, D_IN / 4);

    // layer-1 GEMMs: [*,256] -> [*,512], outputs tf32-rounded
    {
        dim3 gb(D_H / 128, (N_BIZ + 127) / 128);
        sage_mma_kernel<<<gb, 256, SMEM_BYTES>>>(sum_b1, xt_b,
            wt + 0 * 131072, wt + 1 * 131072, b1_ub, h_biz, N_BIZ, D_IN, D_H, 1);
        dim3 gu(D_H / 128, (N_USER + 127) / 128);
        sage_mma_kernel<<<gu, 256, SMEM_BYTES>>>(sum_u1, xt_u,
            wt + 2 * 131072, wt + 3 * 131072, b1_bu, h_user, N_USER, D_IN, D_H, 1);
    }

    // layer-2 aggregation
    gather_mean_kernel<<<N_BIZ, D_H / 4>>>((const float4*)h_user, off_b, adj_b,
                                           inv_b, (float4*)sum_b2, D_H / 4);
    gather_mean_kernel<<<N_USER, D_H / 4>>>((const float4*)h_biz, off_u, adj_u,
                                            inv_u, (float4*)sum_u2, D_H / 4);

    // layer-2 GEMMs: [*,512] -> [*,256], fp32 outputs
    {
        dim3 gb(D_OUT / 128, (N_BIZ + 127) / 128);
        sage_mma_kernel<<<gb, 256, SMEM_BYTES>>>(sum_b2, h_biz,
            wt + 4 * 131072, wt + 5 * 131072, b2_ub, o_biz, N_BIZ, D_H, D_OUT, 0);
        dim3 gu(D_OUT / 128, (N_USER + 127) / 128);
        sage_mma_kernel<<<gu, 256, SMEM_BYTES>>>(sum_u2, h_user,
            wt + 6 * 131072, wt + 7 * 131072, b2_bu, o_user, N_USER, D_H, D_OUT, 0);
    }
}